// round 1
// baseline (speedup 1.0000x reference)
#include <cuda_runtime.h>

// Problem constants (shapes fixed by the dataset)
#define BB     16
#define SS     16
#define DD     4096
#define HH     32
#define KVH    8
#define HDD    128
#define STARTP 4080
#define KVLEN  4096

// Scratch (device globals; no allocations allowed)
__device__ float g_qkv[256 * 6144];   // [m, 0:4096]=q, [4096:5120]=k, [5120:6144]=v (post-RoPE)
__device__ float g_attn[256 * 4096];  // attention output [b*16+q, h*128+d]

// ---------------------------------------------------------------------------
// SGEMM: C[M,N] = A[M,4096] * B[4096,N] + bias, row-major.
// BM=128, BN=64, BK=16, 256 threads, 8x4 per thread.
// Column-range dispatch lets one launch fuse wq|wk|wv.
// ---------------------------------------------------------------------------
__global__ __launch_bounds__(256) void sgemm_kernel(
    const float* __restrict__ A,
    const float* __restrict__ B0, int ldb0, const float* __restrict__ bias0, int split1,
    const float* __restrict__ B1, int ldb1, const float* __restrict__ bias1, int split2,
    const float* __restrict__ B2, int ldb2, const float* __restrict__ bias2,
    float* __restrict__ C, int ldc)
{
    __shared__ float As[16][132];   // A tile transposed, padded
    __shared__ float Bs[16][64];

    const int K = 4096;
    const int n0 = blockIdx.x * 64;
    const int m0 = blockIdx.y * 128;

    const float* Bp; int ldb; const float* bias; int nloc;
    if (n0 < split1)      { Bp = B0; ldb = ldb0; bias = bias0; nloc = n0; }
    else if (n0 < split2) { Bp = B1; ldb = ldb1; bias = bias1; nloc = n0 - split1; }
    else                  { Bp = B2; ldb = ldb2; bias = bias2; nloc = n0 - split2; }

    const int tid = threadIdx.x;
    const int tx = tid & 15;   // 16 col groups of 4
    const int ty = tid >> 4;   // 16 row groups of 8

    float acc[8][4];
    #pragma unroll
    for (int i = 0; i < 8; ++i)
        #pragma unroll
        for (int j = 0; j < 4; ++j) acc[i][j] = 0.f;

    for (int k0 = 0; k0 < K; k0 += 16) {
        // Load A tile (128x16) transposed into As
        #pragma unroll
        for (int p = 0; p < 2; ++p) {
            int id  = tid + p * 256;
            int row = id >> 2;
            int c4  = (id & 3) << 2;
            float4 v = *(const float4*)(A + (size_t)(m0 + row) * K + k0 + c4);
            As[c4 + 0][row] = v.x;
            As[c4 + 1][row] = v.y;
            As[c4 + 2][row] = v.z;
            As[c4 + 3][row] = v.w;
        }
        // Load B tile (16x64)
        {
            int row = tid >> 4;
            int c4  = (tid & 15) << 2;
            *(float4*)&Bs[row][c4] =
                *(const float4*)(Bp + (size_t)(k0 + row) * ldb + nloc + c4);
        }
        __syncthreads();

        #pragma unroll
        for (int kk = 0; kk < 16; ++kk) {
            float a[8], bb[4];
            *(float4*)&a[0] = *(const float4*)&As[kk][ty * 8];
            *(float4*)&a[4] = *(const float4*)&As[kk][ty * 8 + 4];
            *(float4*)&bb[0] = *(const float4*)&Bs[kk][tx * 4];
            #pragma unroll
            for (int i = 0; i < 8; ++i)
                #pragma unroll
                for (int j = 0; j < 4; ++j)
                    acc[i][j] = fmaf(a[i], bb[j], acc[i][j]);
        }
        __syncthreads();
    }

    float4 bv4;
    bv4.x = bias[nloc + tx * 4 + 0];
    bv4.y = bias[nloc + tx * 4 + 1];
    bv4.z = bias[nloc + tx * 4 + 2];
    bv4.w = bias[nloc + tx * 4 + 3];

    #pragma unroll
    for (int i = 0; i < 8; ++i) {
        int m = m0 + ty * 8 + i;
        float4 r;
        r.x = acc[i][0] + bv4.x;
        r.y = acc[i][1] + bv4.y;
        r.z = acc[i][2] + bv4.z;
        r.w = acc[i][3] + bv4.w;
        *(float4*)(C + (size_t)m * ldc + n0 + tx * 4) = r;
    }
}

// ---------------------------------------------------------------------------
// RoPE over q (cols 0:4096) and k (cols 4096:5120) of g_qkv, in place.
// Consecutive-pair complex rotation, cos/sin indexed by (s, hd/2).
// ---------------------------------------------------------------------------
__global__ __launch_bounds__(256) void rope_kernel(
    float* __restrict__ qkv,
    const float* __restrict__ cos_t,
    const float* __restrict__ sin_t)
{
    int gid = blockIdx.x * 256 + threadIdx.x;   // 256 rows * 2560 pairs
    int m = gid / 2560;
    int j = gid - m * 2560;
    int s = m & 15;
    int col, p;
    if (j < 2048) { col = 2 * j;               p = j & 63; }
    else          { int jj = j - 2048; col = 4096 + 2 * jj; p = jj & 63; }
    float c  = cos_t[s * 64 + p];
    float sn = sin_t[s * 64 + p];
    float* ptr = qkv + (size_t)m * 6144 + col;
    float xr = ptr[0], xi = ptr[1];
    ptr[0] = xr * c - xi * sn;
    ptr[1] = xr * sn + xi * c;
}

// ---------------------------------------------------------------------------
// Flash attention: one block per (batch, kv_head). 64 q-rows (4 rep heads x
// 16 positions) share one K/V stream of 4096 keys (tiles of 32).
// Thread layout: g = tid/8 owns rows 2g,2g+1; c = tid%8 owns 4 keys (QK)
// and dims d = 4*(c+8u) (PV). Online softmax per row, dup'd across 8 lanes.
// ---------------------------------------------------------------------------
__global__ __launch_bounds__(256) void attn_kernel(
    const float* __restrict__ cache_k,
    const float* __restrict__ cache_v,
    const float* __restrict__ qkv,
    float* __restrict__ attn_out)
{
    extern __shared__ float sm[];
    float* q_s = sm;                 // 64 x 128
    float* k_s = q_s + 64 * 128;     // 32 x 132 (padded: conflict-free QK reads)
    float* v_s = k_s + 32 * 132;     // 32 x 128
    float* p_s = v_s + 32 * 128;     // 64 x 33

    const int tid = threadIdx.x;
    const int b   = blockIdx.x >> 3;
    const int kvh = blockIdx.x & 7;
    const float scale = 0.08838834764831843f;   // 1/sqrt(128)

    // Load + scale Q tile
    for (int i = tid; i < 64 * 32; i += 256) {
        int r  = i >> 5;
        int c4 = (i & 31) << 2;
        int hl = r >> 4, qi = r & 15;
        float4 v = *(const float4*)(qkv + (size_t)(b * 16 + qi) * 6144
                                    + (kvh * 4 + hl) * 128 + c4);
        v.x *= scale; v.y *= scale; v.z *= scale; v.w *= scale;
        *(float4*)&q_s[r * 128 + c4] = v;
    }

    const int g  = tid >> 3;
    const int c  = tid & 7;
    const int r0 = 2 * g, r1 = r0 + 1;
    const int qi0 = r0 & 15, qi1 = r1 & 15;

    float o0[16], o1[16];
    #pragma unroll
    for (int i = 0; i < 16; ++i) { o0[i] = 0.f; o1[i] = 0.f; }
    float m0 = -1e30f, m1 = -1e30f, l0 = 0.f, l1 = 0.f;

    __syncthreads();

    for (int t = 0; t < 128; ++t) {
        const int key0 = t << 5;
        __syncthreads();    // prior tile's PV done before overwriting k_s/v_s

        // Load K/V tile (32 keys x 128). Fresh rows (>= STARTP) come from g_qkv.
        for (int i = tid; i < 1024; i += 256) {
            int kr  = i >> 5;
            int c4  = (i & 31) << 2;
            int key = key0 + kr;
            const float *ksrc, *vsrc;
            if (key < STARTP) {
                size_t base = ((size_t)(b * 4096 + key) * 8 + kvh) * 128;
                ksrc = cache_k + base;
                vsrc = cache_v + base;
            } else {
                size_t row = (size_t)(b * 16 + (key - STARTP)) * 6144;
                ksrc = qkv + row + 4096 + kvh * 128;
                vsrc = qkv + row + 5120 + kvh * 128;
            }
            *(float4*)&k_s[kr * 132 + c4] = *(const float4*)(ksrc + c4);
            *(float4*)&v_s[kr * 128 + c4] = *(const float4*)(vsrc + c4);
        }
        __syncthreads();

        // QK^T: rows r0,r1 vs keys {c, c+8, c+16, c+24}
        float acc0[4], acc1[4];
        #pragma unroll
        for (int mm = 0; mm < 4; ++mm) { acc0[mm] = 0.f; acc1[mm] = 0.f; }
        const float4* q0p = (const float4*)&q_s[r0 * 128];
        const float4* q1p = (const float4*)&q_s[r1 * 128];
        #pragma unroll 4
        for (int kk4 = 0; kk4 < 32; ++kk4) {
            float4 q0 = q0p[kk4];
            float4 q1 = q1p[kk4];
            #pragma unroll
            for (int mm = 0; mm < 4; ++mm) {
                float4 kv = *(const float4*)&k_s[(c + 8 * mm) * 132 + (kk4 << 2)];
                acc0[mm] = fmaf(q0.x, kv.x, fmaf(q0.y, kv.y,
                           fmaf(q0.z, kv.z, fmaf(q0.w, kv.w, acc0[mm]))));
                acc1[mm] = fmaf(q1.x, kv.x, fmaf(q1.y, kv.y,
                           fmaf(q1.z, kv.z, fmaf(q1.w, kv.w, acc1[mm]))));
            }
        }

        if (t == 127) {   // causal mask only touches the last tile
            #pragma unroll
            for (int mm = 0; mm < 4; ++mm) {
                int key = key0 + c + 8 * mm;
                if (key > STARTP + qi0) acc0[mm] = -1e30f;
                if (key > STARTP + qi1) acc1[mm] = -1e30f;
            }
        }

        // Online softmax (reduce across the 8 lanes owning each row pair)
        float tmax0 = fmaxf(fmaxf(acc0[0], acc0[1]), fmaxf(acc0[2], acc0[3]));
        float tmax1 = fmaxf(fmaxf(acc1[0], acc1[1]), fmaxf(acc1[2], acc1[3]));
        #pragma unroll
        for (int off = 1; off < 8; off <<= 1) {
            tmax0 = fmaxf(tmax0, __shfl_xor_sync(0xffffffffu, tmax0, off));
            tmax1 = fmaxf(tmax1, __shfl_xor_sync(0xffffffffu, tmax1, off));
        }
        float mn0 = fmaxf(m0, tmax0);
        float mn1 = fmaxf(m1, tmax1);
        float corr0 = __expf(m0 - mn0);
        float corr1 = __expf(m1 - mn1);
        float ps0 = 0.f, ps1 = 0.f;
        #pragma unroll
        for (int mm = 0; mm < 4; ++mm) {
            float p0 = __expf(acc0[mm] - mn0);
            float p1 = __expf(acc1[mm] - mn1);
            ps0 += p0; ps1 += p1;
            p_s[r0 * 33 + c + 8 * mm] = p0;
            p_s[r1 * 33 + c + 8 * mm] = p1;
        }
        #pragma unroll
        for (int off = 1; off < 8; off <<= 1) {
            ps0 += __shfl_xor_sync(0xffffffffu, ps0, off);
            ps1 += __shfl_xor_sync(0xffffffffu, ps1, off);
        }
        l0 = l0 * corr0 + ps0;
        l1 = l1 * corr1 + ps1;
        m0 = mn0; m1 = mn1;
        #pragma unroll
        for (int i = 0; i < 16; ++i) { o0[i] *= corr0; o1[i] *= corr1; }

        __syncwarp();   // p_s produced/consumed within the same warp

        // P @ V: this thread owns dims 4*(c+8u)..+3
        #pragma unroll 4
        for (int key = 0; key < 32; ++key) {
            float p0 = p_s[r0 * 33 + key];
            float p1 = p_s[r1 * 33 + key];
            const float4* vrow = (const float4*)&v_s[key * 128];
            #pragma unroll
            for (int u = 0; u < 4; ++u) {
                float4 vv = vrow[c + 8 * u];
                o0[4 * u + 0] = fmaf(p0, vv.x, o0[4 * u + 0]);
                o0[4 * u + 1] = fmaf(p0, vv.y, o0[4 * u + 1]);
                o0[4 * u + 2] = fmaf(p0, vv.z, o0[4 * u + 2]);
                o0[4 * u + 3] = fmaf(p0, vv.w, o0[4 * u + 3]);
                o1[4 * u + 0] = fmaf(p1, vv.x, o1[4 * u + 0]);
                o1[4 * u + 1] = fmaf(p1, vv.y, o1[4 * u + 1]);
                o1[4 * u + 2] = fmaf(p1, vv.z, o1[4 * u + 2]);
                o1[4 * u + 3] = fmaf(p1, vv.w, o1[4 * u + 3]);
            }
        }
    }

    // Finalize + store
    float inv0 = 1.f / l0;
    float inv1 = 1.f / l1;
    int hl0 = r0 >> 4, hl1 = r1 >> 4;
    size_t base0 = (size_t)(b * 16 + qi0) * 4096 + (kvh * 4 + hl0) * 128;
    size_t base1 = (size_t)(b * 16 + qi1) * 4096 + (kvh * 4 + hl1) * 128;
    #pragma unroll
    for (int u = 0; u < 4; ++u) {
        float4 w0, w1;
        w0.x = o0[4 * u + 0] * inv0; w0.y = o0[4 * u + 1] * inv0;
        w0.z = o0[4 * u + 2] * inv0; w0.w = o0[4 * u + 3] * inv0;
        w1.x = o1[4 * u + 0] * inv1; w1.y = o1[4 * u + 1] * inv1;
        w1.z = o1[4 * u + 2] * inv1; w1.w = o1[4 * u + 3] * inv1;
        *(float4*)(attn_out + base0 + (size_t)(c + 8 * u) * 4) = w0;
        *(float4*)(attn_out + base1 + (size_t)(c + 8 * u) * 4) = w1;
    }
}

// ---------------------------------------------------------------------------
extern "C" void kernel_launch(void* const* d_in, const int* in_sizes, int n_in,
                              void* d_out, int out_size)
{
    const float* x  = (const float*)d_in[0];
    const float* fc = (const float*)d_in[1];
    const float* fs = (const float*)d_in[2];
    // d_in[3] = mask (causality handled analytically)
    const float* ck = (const float*)d_in[4];
    const float* cv = (const float*)d_in[5];
    const float* wq = (const float*)d_in[6];
    const float* bq = (const float*)d_in[7];
    const float* wk = (const float*)d_in[8];
    const float* bk = (const float*)d_in[9];
    const float* wv = (const float*)d_in[10];
    const float* bv = (const float*)d_in[11];
    const float* wo = (const float*)d_in[12];
    const float* bo = (const float*)d_in[13];
    // d_in[14] = start_pos (fixed at 4080 for this problem)
    float* out = (float*)d_out;

    float *qkv, *attn;
    cudaGetSymbolAddress((void**)&qkv, g_qkv);
    cudaGetSymbolAddress((void**)&attn, g_attn);

    const int attn_smem = (64 * 128 + 32 * 132 + 32 * 128 + 64 * 33) * 4; // 74496 B
    cudaFuncSetAttribute(attn_kernel,
                         cudaFuncAttributeMaxDynamicSharedMemorySize, attn_smem);

    // Fused QKV projection: C[256,6144] = x @ [wq|wk|wv] + [bq|bk|bv]
    sgemm_kernel<<<dim3(96, 2), 256>>>(
        x,
        wq, 4096, bq, 4096,
        wk, 1024, bk, 5120,
        wv, 1024, bv,
        qkv, 6144);

    // RoPE on q and k
    rope_kernel<<<2560, 256>>>(qkv, fc, fs);

    // Attention: 128 blocks = (16 batches x 8 kv heads)
    attn_kernel<<<128, 256, attn_smem>>>(ck, cv, qkv, attn);

    // Output projection: out = attn @ wo + bo
    sgemm_kernel<<<dim3(64, 2), 256>>>(
        attn,
        wo, 4096, bo, 1 << 30,
        wo, 4096, bo, 1 << 30,
        wo, 4096, bo,
        out, 4096);
}

// round 3
// speedup vs baseline: 2.8633x; 2.8633x over previous
#include <cuda_runtime.h>
#include <cuda_bf16.h>
#include <cstdint>

#define STARTP 4080

// ---------------------------------------------------------------------------
// Device-global scratch (no allocations allowed)
// ---------------------------------------------------------------------------
__device__ float g_qkv[256 * 6144];                                   // fp32 q|k|v
__device__ __nv_bfloat16 g_wq_h[4096*4096], g_wq_l[4096*4096];
__device__ __nv_bfloat16 g_wk_h[4096*1024], g_wk_l[4096*1024];
__device__ __nv_bfloat16 g_wv_h[4096*1024], g_wv_l[4096*1024];
__device__ __nv_bfloat16 g_wo_h[4096*4096], g_wo_l[4096*4096];
__device__ __nv_bfloat16 g_x_h [256*4096],  g_x_l [256*4096];
__device__ __nv_bfloat16 g_at_h[256*4096],  g_at_l[256*4096];

// ---------------------------------------------------------------------------
// helpers
// ---------------------------------------------------------------------------
__device__ __forceinline__ uint32_t packbf(float a, float b) {  // a->lo16, b->hi16
    uint32_t u;
    asm("cvt.rn.bf16x2.f32 %0, %1, %2;" : "=r"(u) : "f"(b), "f"(a));
    return u;
}
// split pair (a,b) into bf16-hi plane word and bf16-lo (residual) plane word
__device__ __forceinline__ void split2(float a, float b, uint32_t& h, uint32_t& l) {
    h = packbf(a, b);
    float ra = a - __uint_as_float(h << 16);
    float rb = b - __uint_as_float(h & 0xffff0000u);
    l = packbf(ra, rb);
}

__device__ __forceinline__ void mma16(float* c, const uint32_t* a,
                                      uint32_t b0, uint32_t b1) {
    asm("mma.sync.aligned.m16n8k16.row.col.f32.bf16.bf16.f32 "
        "{%0,%1,%2,%3}, {%4,%5,%6,%7}, {%8,%9}, {%0,%1,%2,%3};"
        : "+f"(c[0]), "+f"(c[1]), "+f"(c[2]), "+f"(c[3])
        : "r"(a[0]), "r"(a[1]), "r"(a[2]), "r"(a[3]), "r"(b0), "r"(b1));
}

__device__ __forceinline__ void ldsm4(uint32_t* r, uint32_t addr) {
    asm volatile("ldmatrix.sync.aligned.m8n8.x4.shared.b16 {%0,%1,%2,%3}, [%4];"
        : "=r"(r[0]), "=r"(r[1]), "=r"(r[2]), "=r"(r[3]) : "r"(addr));
}
__device__ __forceinline__ void ldsm4t(uint32_t* r, uint32_t addr) {
    asm volatile("ldmatrix.sync.aligned.m8n8.x4.trans.shared.b16 {%0,%1,%2,%3}, [%4];"
        : "=r"(r[0]), "=r"(r[1]), "=r"(r[2]), "=r"(r[3]) : "r"(addr));
}
__device__ __forceinline__ void cp16(uint32_t s, const void* g) {
    asm volatile("cp.async.cg.shared.global [%0], [%1], 16;" :: "r"(s), "l"(g));
}
#define CP_COMMIT asm volatile("cp.async.commit_group;")
#define CP_WAIT1  asm volatile("cp.async.wait_group 1;")
#define CP_WAIT0  asm volatile("cp.async.wait_group 0;")

// ---------------------------------------------------------------------------
// fp32 -> bf16 hi/lo planes (vectorized, once per launch)
// ---------------------------------------------------------------------------
__global__ __launch_bounds__(256) void convert_kernel(
    const float* __restrict__ in, __nv_bfloat16* __restrict__ oh,
    __nv_bfloat16* __restrict__ ol, int n4)
{
    int i = blockIdx.x * 256 + threadIdx.x;
    if (i >= n4) return;
    float4 v = ((const float4*)in)[i];
    uint32_t h0, l0, h1, l1;
    split2(v.x, v.y, h0, l0);
    split2(v.z, v.w, h1, l1);
    ((uint2*)oh)[i] = make_uint2(h0, h1);
    ((uint2*)ol)[i] = make_uint2(l0, l1);
}

// ---------------------------------------------------------------------------
// bf16x3 GEMM: C[M,N] = A[M,4096] @ B[4096,N] + bias (fp32 out).
// Block 64M x 128N, BK=32, 128 thr (warps 2m x 2n). A/B pre-split planes.
// ---------------------------------------------------------------------------
__global__ __launch_bounds__(128) void gemm_bf16x3(
    const __nv_bfloat16* __restrict__ Ah, const __nv_bfloat16* __restrict__ Al,
    const __nv_bfloat16* B0h, const __nv_bfloat16* B0l, int ldb0, const float* bias0, int split1,
    const __nv_bfloat16* B1h, const __nv_bfloat16* B1l, int ldb1, const float* bias1, int split2_,
    const __nv_bfloat16* B2h, const __nv_bfloat16* B2l, int ldb2, const float* bias2,
    float* __restrict__ C, int ldc)
{
    extern __shared__ char smraw[];
    __nv_bfloat16* As = (__nv_bfloat16*)smraw;      // [2][2][64][40]
    __nv_bfloat16* Bs = As + 2*2*64*40;             // [2][2][32][136]

    const int n0 = blockIdx.x * 128;
    const int m0 = blockIdx.y * 64;

    const __nv_bfloat16 *Bph, *Bpl; int ldb; const float* bias; int nloc;
    if (n0 < split1)       { Bph = B0h; Bpl = B0l; ldb = ldb0; bias = bias0; nloc = n0; }
    else if (n0 < split2_) { Bph = B1h; Bpl = B1l; ldb = ldb1; bias = bias1; nloc = n0 - split1; }
    else                   { Bph = B2h; Bpl = B2l; ldb = ldb2; bias = bias2; nloc = n0 - split2_; }

    const int tid = threadIdx.x, lane = tid & 31, warp = tid >> 5;
    const int g = lane >> 2, tig = lane & 3;
    const int wm = warp & 1, wn = warp >> 1;
    const int lr = lane & 7, mt = lane >> 3;

    const uint32_t sA = (uint32_t)__cvta_generic_to_shared(As);
    const uint32_t sB = (uint32_t)__cvta_generic_to_shared(Bs);

    float acc[2][8][4];
    #pragma unroll
    for (int mf = 0; mf < 2; ++mf)
        #pragma unroll
        for (int nf = 0; nf < 8; ++nf)
            #pragma unroll
            for (int j = 0; j < 4; ++j) acc[mf][nf][j] = 0.f;

    auto load = [&](int ck, int s) {
        // A planes: 2 x 64 rows x 4 seg(16B)
        #pragma unroll
        for (int i = 0; i < 4; ++i) {
            int idx = tid + 128 * i;
            int p = idx >> 8, rem = idx & 255, row = rem >> 2, seg = rem & 3;
            const __nv_bfloat16* src = (p ? Al : Ah)
                + (size_t)(m0 + row) * 4096 + ck * 32 + seg * 8;
            uint32_t dst = sA + (uint32_t)((((s*2+p)*64 + row)*40 + seg*8) * 2);
            cp16(dst, src);
        }
        // B planes: 2 x 32 rows x 16 seg
        #pragma unroll
        for (int i = 0; i < 8; ++i) {
            int idx = tid + 128 * i;
            int p = idx >> 9, rem = idx & 511, row = rem >> 4, seg = rem & 15;
            const __nv_bfloat16* src = (p ? Bpl : Bph)
                + (size_t)(ck * 32 + row) * ldb + nloc + seg * 8;
            uint32_t dst = sB + (uint32_t)((((s*2+p)*32 + row)*136 + seg*8) * 2);
            cp16(dst, src);
        }
    };

    load(0, 0); CP_COMMIT;

    for (int ck = 0; ck < 128; ++ck) {
        int s = ck & 1;
        if (ck + 1 < 128) { load(ck + 1, s ^ 1); CP_COMMIT; CP_WAIT1; }
        else              { CP_WAIT0; }
        __syncthreads();

        #pragma unroll
        for (int ks = 0; ks < 2; ++ks) {
            int k0 = ks * 16;
            uint32_t ah[2][4], al[2][4];
            #pragma unroll
            for (int mf = 0; mf < 2; ++mf) {
                int row = wm*32 + mf*16 + (mt & 1)*8 + lr;
                int col = k0 + (mt >> 1)*8;
                ldsm4(ah[mf], sA + (uint32_t)((((s*2+0)*64 + row)*40 + col)*2));
                ldsm4(al[mf], sA + (uint32_t)((((s*2+1)*64 + row)*40 + col)*2));
            }
            #pragma unroll
            for (int nfp = 0; nfp < 4; ++nfp) {
                int row = k0 + (mt & 1)*8 + lr;
                int col = wn*64 + (nfp*2 + (mt >> 1))*8;
                uint32_t bh[4], bl[4];
                ldsm4t(bh, sB + (uint32_t)((((s*2+0)*32 + row)*136 + col)*2));
                ldsm4t(bl, sB + (uint32_t)((((s*2+1)*32 + row)*136 + col)*2));
                #pragma unroll
                for (int h = 0; h < 2; ++h) {
                    int nf = nfp*2 + h;
                    #pragma unroll
                    for (int mf = 0; mf < 2; ++mf) {
                        mma16(acc[mf][nf], ah[mf], bh[2*h], bh[2*h+1]);
                        mma16(acc[mf][nf], ah[mf], bl[2*h], bl[2*h+1]);
                        mma16(acc[mf][nf], al[mf], bh[2*h], bh[2*h+1]);
                    }
                }
            }
        }
        __syncthreads();
    }

    #pragma unroll
    for (int mf = 0; mf < 2; ++mf) {
        int r0 = m0 + wm*32 + mf*16 + g;
        #pragma unroll
        for (int nf = 0; nf < 8; ++nf) {
            int cl = wn*64 + nf*8 + 2*tig;
            float b0v = bias[nloc + cl], b1v = bias[nloc + cl + 1];
            float2 w0, w1;
            w0.x = acc[mf][nf][0] + b0v; w0.y = acc[mf][nf][1] + b1v;
            w1.x = acc[mf][nf][2] + b0v; w1.y = acc[mf][nf][3] + b1v;
            *(float2*)(C + (size_t)r0 * ldc + n0 + cl)       = w0;
            *(float2*)(C + (size_t)(r0 + 8) * ldc + n0 + cl) = w1;
        }
    }
}

// ---------------------------------------------------------------------------
// RoPE over q (cols 0:4096) and k (cols 4096:5120) of g_qkv, in place.
// ---------------------------------------------------------------------------
__global__ __launch_bounds__(256) void rope_kernel(
    const float* __restrict__ cos_t, const float* __restrict__ sin_t)
{
    int gid = blockIdx.x * 256 + threadIdx.x;
    int m = gid / 2560;
    int j = gid - m * 2560;
    int s = m & 15;
    int col, p;
    if (j < 2048) { col = 2 * j;               p = j & 63; }
    else          { int jj = j - 2048; col = 4096 + 2 * jj; p = jj & 63; }
    float c  = cos_t[s * 64 + p];
    float sn = sin_t[s * 64 + p];
    float* ptr = g_qkv + (size_t)m * 6144 + col;
    float xr = ptr[0], xi = ptr[1];
    ptr[0] = xr * c - xi * sn;
    ptr[1] = xr * sn + xi * c;
}

// ---------------------------------------------------------------------------
// bf16x3 flash attention. Block = (b, kvh); 4 warps, warp w = head kvh*4+w.
// K/V converted to bf16 hi/lo planes in producer; P stays in registers.
// Output written directly as bf16 hi/lo planes for the out-projection.
// ---------------------------------------------------------------------------
__global__ __launch_bounds__(128, 1) void attn_bf16x3(
    const float* __restrict__ cache_k, const float* __restrict__ cache_v)
{
    extern __shared__ char smraw[];
    __nv_bfloat16* Kh = (__nv_bfloat16*)smraw;   // [2][64][136]
    __nv_bfloat16* Kl = Kh + 2*8704;
    __nv_bfloat16* Vh = Kl + 2*8704;
    __nv_bfloat16* Vl = Vh + 2*8704;
    float* Qs = (float*)smraw;                   // staging only (pre-loop)

    const int tid = threadIdx.x, lane = tid & 31, w = tid >> 5;
    const int g = lane >> 2, tig = lane & 3;
    const int lr = lane & 7, mt = lane >> 3;
    const int b = blockIdx.x >> 3, kvh = blockIdx.x & 7;
    const float scale = 0.08838834764831843f;   // 1/sqrt(128)
    const float* qkv = g_qkv;

    // ---- stage Q (scaled fp32), lift to bf16 hi/lo fragments ----
    for (int i = tid; i < 64 * 32; i += 128) {
        int r = i >> 5, c4 = (i & 31) << 2;
        const float* src = qkv + (size_t)(b * 16 + (r & 15)) * 6144
                         + (kvh * 4 + (r >> 4)) * 128 + c4;
        float4 v = *(const float4*)src;
        Qs[r * 132 + c4 + 0] = v.x * scale;
        Qs[r * 132 + c4 + 1] = v.y * scale;
        Qs[r * 132 + c4 + 2] = v.z * scale;
        Qs[r * 132 + c4 + 3] = v.w * scale;
    }
    __syncthreads();

    uint32_t qh[8][4], ql[8][4];
    #pragma unroll
    for (int kk = 0; kk < 8; ++kk) {
        const float* r0 = Qs + (w*16 + g    ) * 132 + kk*16;
        const float* r1 = Qs + (w*16 + g + 8) * 132 + kk*16;
        split2(r0[2*tig],     r0[2*tig + 1], qh[kk][0], ql[kk][0]);
        split2(r1[2*tig],     r1[2*tig + 1], qh[kk][1], ql[kk][1]);
        split2(r0[2*tig + 8], r0[2*tig + 9], qh[kk][2], ql[kk][2]);
        split2(r1[2*tig + 8], r1[2*tig + 9], qh[kk][3], ql[kk][3]);
    }
    __syncthreads();

    const uint32_t kh_b = (uint32_t)__cvta_generic_to_shared(Kh);
    const uint32_t kl_b = (uint32_t)__cvta_generic_to_shared(Kl);
    const uint32_t vh_b = (uint32_t)__cvta_generic_to_shared(Vh);
    const uint32_t vl_b = (uint32_t)__cvta_generic_to_shared(Vl);

    float oacc[16][4];
    #pragma unroll
    for (int i = 0; i < 16; ++i)
        #pragma unroll
        for (int j = 0; j < 4; ++j) oacc[i][j] = 0.f;
    float mA = -1e30f, mB = -1e30f, lA = 0.f, lB = 0.f;

    // producer: load fp32 K/V tile, convert, store bf16 planes
    auto produce = [&](int t) {
        int s = t & 1;
        #pragma unroll 4
        for (int i = 0; i < 16; ++i) {
            int id = tid + 128 * i;
            int row = id >> 5, c4 = (id & 31) << 2;
            int key = t * 64 + row;
            const float *ks, *vs;
            if (key < STARTP) {
                size_t base = ((size_t)(b * 4096 + key) * 8 + kvh) * 128 + c4;
                ks = cache_k + base; vs = cache_v + base;
            } else {
                size_t rb = (size_t)(b * 16 + key - STARTP) * 6144 + kvh * 128 + c4;
                ks = qkv + rb + 4096; vs = qkv + rb + 5120;
            }
            float4 kv = *(const float4*)ks;
            float4 vv = *(const float4*)vs;
            uint32_t h0, l0, h1, l1;
            int e = s * 8704 + row * 136 + c4;
            split2(kv.x, kv.y, h0, l0); split2(kv.z, kv.w, h1, l1);
            *(uint32_t*)&Kh[e] = h0; *(uint32_t*)&Kh[e + 2] = h1;
            *(uint32_t*)&Kl[e] = l0; *(uint32_t*)&Kl[e + 2] = l1;
            split2(vv.x, vv.y, h0, l0); split2(vv.z, vv.w, h1, l1);
            *(uint32_t*)&Vh[e] = h0; *(uint32_t*)&Vh[e + 2] = h1;
            *(uint32_t*)&Vl[e] = l0; *(uint32_t*)&Vl[e + 2] = l1;
        }
    };

    produce(0);
    __syncthreads();

    for (int t = 0; t < 64; ++t) {
        int s = t & 1;
        if (t + 1 < 64) produce(t + 1);   // fills stage s^1

        // ---- S = Q K^T (warp: 16 rows x 64 keys) ----
        float sacc[8][4];
        #pragma unroll
        for (int nf = 0; nf < 8; ++nf)
            #pragma unroll
            for (int j = 0; j < 4; ++j) sacc[nf][j] = 0.f;

        #pragma unroll
        for (int kk = 0; kk < 8; ++kk) {
            #pragma unroll
            for (int nfp = 0; nfp < 4; ++nfp) {
                int row = (nfp*2 + (mt >> 1))*8 + lr;          // key
                int col = kk*16 + (mt & 1)*8;                  // hd
                uint32_t off = (uint32_t)((s*8704 + row*136 + col)*2);
                uint32_t bh[4], bl[4];
                ldsm4(bh, kh_b + off);
                ldsm4(bl, kl_b + off);
                #pragma unroll
                for (int h = 0; h < 2; ++h) {
                    int nf = nfp*2 + h;
                    mma16(sacc[nf], qh[kk], bh[2*h], bh[2*h+1]);
                    mma16(sacc[nf], qh[kk], bl[2*h], bl[2*h+1]);
                    mma16(sacc[nf], ql[kk], bh[2*h], bh[2*h+1]);
                }
            }
        }

        if (t == 63) {  // causal mask, analytic
            #pragma unroll
            for (int nf = 0; nf < 8; ++nf) {
                int key = 4032 + nf * 8 + 2 * tig;
                if (key     > STARTP + g)     sacc[nf][0] = -1e30f;
                if (key + 1 > STARTP + g)     sacc[nf][1] = -1e30f;
                if (key     > STARTP + g + 8) sacc[nf][2] = -1e30f;
                if (key + 1 > STARTP + g + 8) sacc[nf][3] = -1e30f;
            }
        }

        // ---- online softmax (rows g and g+8); reduce over tig lanes ----
        float tmA = -1e30f, tmB = -1e30f;
        #pragma unroll
        for (int nf = 0; nf < 8; ++nf) {
            tmA = fmaxf(tmA, fmaxf(sacc[nf][0], sacc[nf][1]));
            tmB = fmaxf(tmB, fmaxf(sacc[nf][2], sacc[nf][3]));
        }
        tmA = fmaxf(tmA, __shfl_xor_sync(0xffffffffu, tmA, 1));
        tmA = fmaxf(tmA, __shfl_xor_sync(0xffffffffu, tmA, 2));
        tmB = fmaxf(tmB, __shfl_xor_sync(0xffffffffu, tmB, 1));
        tmB = fmaxf(tmB, __shfl_xor_sync(0xffffffffu, tmB, 2));

        float mnA = fmaxf(mA, tmA), mnB = fmaxf(mB, tmB);
        float cA = __expf(mA - mnA), cB = __expf(mB - mnB);
        float psA = 0.f, psB = 0.f;
        #pragma unroll
        for (int nf = 0; nf < 8; ++nf) {
            sacc[nf][0] = __expf(sacc[nf][0] - mnA);
            sacc[nf][1] = __expf(sacc[nf][1] - mnA);
            sacc[nf][2] = __expf(sacc[nf][2] - mnB);
            sacc[nf][3] = __expf(sacc[nf][3] - mnB);
            psA += sacc[nf][0] + sacc[nf][1];
            psB += sacc[nf][2] + sacc[nf][3];
        }
        psA += __shfl_xor_sync(0xffffffffu, psA, 1);
        psA += __shfl_xor_sync(0xffffffffu, psA, 2);
        psB += __shfl_xor_sync(0xffffffffu, psB, 1);
        psB += __shfl_xor_sync(0xffffffffu, psB, 2);
        lA = lA * cA + psA; lB = lB * cB + psB;
        mA = mnA; mB = mnB;
        #pragma unroll
        for (int i = 0; i < 16; ++i) {
            oacc[i][0] *= cA; oacc[i][1] *= cA;
            oacc[i][2] *= cB; oacc[i][3] *= cB;
        }

        // ---- O += P V (P fragments straight from sacc registers) ----
        #pragma unroll
        for (int kf = 0; kf < 4; ++kf) {
            uint32_t pah[4], pal[4];
            split2(sacc[2*kf][0],   sacc[2*kf][1],   pah[0], pal[0]);
            split2(sacc[2*kf][2],   sacc[2*kf][3],   pah[1], pal[1]);
            split2(sacc[2*kf+1][0], sacc[2*kf+1][1], pah[2], pal[2]);
            split2(sacc[2*kf+1][2], sacc[2*kf+1][3], pah[3], pal[3]);
            #pragma unroll
            for (int np = 0; np < 8; ++np) {
                int row = kf*16 + (mt & 1)*8 + lr;             // key
                int col = (np*2 + (mt >> 1))*8;                // d
                uint32_t off = (uint32_t)((s*8704 + row*136 + col)*2);
                uint32_t vh[4], vl[4];
                ldsm4t(vh, vh_b + off);
                ldsm4t(vl, vl_b + off);
                #pragma unroll
                for (int h = 0; h < 2; ++h) {
                    int nf2 = np*2 + h;
                    mma16(oacc[nf2], pah, vh[2*h], vh[2*h+1]);
                    mma16(oacc[nf2], pah, vl[2*h], vl[2*h+1]);
                    mma16(oacc[nf2], pal, vh[2*h], vh[2*h+1]);
                }
            }
        }
        __syncthreads();   // stage s fully consumed; s^1 stores visible
    }

    // ---- finalize: write bf16 hi/lo planes for out-projection ----
    float rAi = 1.f / lA, rBi = 1.f / lB;
    size_t baseA = (size_t)(b*16 + g    ) * 4096 + (kvh*4 + w) * 128;
    size_t baseB = (size_t)(b*16 + g + 8) * 4096 + (kvh*4 + w) * 128;
    #pragma unroll
    for (int nf2 = 0; nf2 < 16; ++nf2) {
        int col = nf2*8 + 2*tig;
        uint32_t h, l;
        split2(oacc[nf2][0]*rAi, oacc[nf2][1]*rAi, h, l);
        *(uint32_t*)&g_at_h[baseA + col] = h;
        *(uint32_t*)&g_at_l[baseA + col] = l;
        split2(oacc[nf2][2]*rBi, oacc[nf2][3]*rBi, h, l);
        *(uint32_t*)&g_at_h[baseB + col] = h;
        *(uint32_t*)&g_at_l[baseB + col] = l;
    }
}

// ---------------------------------------------------------------------------
extern "C" void kernel_launch(void* const* d_in, const int* in_sizes, int n_in,
                              void* d_out, int out_size)
{
    const float* x  = (const float*)d_in[0];
    const float* fc = (const float*)d_in[1];
    const float* fs = (const float*)d_in[2];
    const float* ck = (const float*)d_in[4];
    const float* cv = (const float*)d_in[5];
    const float* wq = (const float*)d_in[6];
    const float* bq = (const float*)d_in[7];
    const float* wk = (const float*)d_in[8];
    const float* bk = (const float*)d_in[9];
    const float* wv = (const float*)d_in[10];
    const float* bv = (const float*)d_in[11];
    const float* wo = (const float*)d_in[12];
    const float* bo = (const float*)d_in[13];
    float* out = (float*)d_out;

    __nv_bfloat16 *wq_h, *wq_l, *wk_h, *wk_l, *wv_h, *wv_l, *wo_h, *wo_l;
    __nv_bfloat16 *x_h, *x_l, *at_h, *at_l;
    float* qkv;
    cudaGetSymbolAddress((void**)&wq_h, g_wq_h); cudaGetSymbolAddress((void**)&wq_l, g_wq_l);
    cudaGetSymbolAddress((void**)&wk_h, g_wk_h); cudaGetSymbolAddress((void**)&wk_l, g_wk_l);
    cudaGetSymbolAddress((void**)&wv_h, g_wv_h); cudaGetSymbolAddress((void**)&wv_l, g_wv_l);
    cudaGetSymbolAddress((void**)&wo_h, g_wo_h); cudaGetSymbolAddress((void**)&wo_l, g_wo_l);
    cudaGetSymbolAddress((void**)&x_h,  g_x_h);  cudaGetSymbolAddress((void**)&x_l,  g_x_l);
    cudaGetSymbolAddress((void**)&at_h, g_at_h); cudaGetSymbolAddress((void**)&at_l, g_at_l);
    cudaGetSymbolAddress((void**)&qkv,  g_qkv);

    const int gemm_smem = (2*2*64*40 + 2*2*32*136) * 2;   // 55296 B
    const int attn_smem = 4 * 2 * 8704 * 2;               // 139264 B
    cudaFuncSetAttribute(gemm_bf16x3,
                         cudaFuncAttributeMaxDynamicSharedMemorySize, gemm_smem);
    cudaFuncSetAttribute(attn_bf16x3,
                         cudaFuncAttributeMaxDynamicSharedMemorySize, attn_smem);

    // 1) split fp32 -> bf16 hi/lo planes
    convert_kernel<<<16384, 256>>>(wq, wq_h, wq_l, 4096*4096/4);
    convert_kernel<<< 4096, 256>>>(wk, wk_h, wk_l, 4096*1024/4);
    convert_kernel<<< 4096, 256>>>(wv, wv_h, wv_l, 4096*1024/4);
    convert_kernel<<<16384, 256>>>(wo, wo_h, wo_l, 4096*4096/4);
    convert_kernel<<< 1024, 256>>>(x,  x_h,  x_l,  256*4096/4);

    // 2) fused QKV projection (fp32 out into g_qkv)
    gemm_bf16x3<<<dim3(48, 4), 128, gemm_smem>>>(
        x_h, x_l,
        wq_h, wq_l, 4096, bq, 4096,
        wk_h, wk_l, 1024, bk, 5120,
        wv_h, wv_l, 1024, bv,
        qkv, 6144);

    // 3) RoPE on q and k
    rope_kernel<<<2560, 256>>>(fc, fs);

    // 4) attention (writes bf16 hi/lo planes)
    attn_bf16x3<<<128, 128, attn_smem>>>(ck, cv);

    // 5) output projection -> d_out (fp32)
    gemm_bf16x3<<<dim3(32, 4), 128, gemm_smem>>>(
        at_h, at_l,
        wo_h, wo_l, 4096, bo, 1 << 30,
        wo_h, wo_l, 4096, bo, 1 << 30,
        wo_h, wo_l, 4096, bo,
        out, 4096);
}

// round 4
// speedup vs baseline: 3.7174x; 1.2983x over previous
#include <cuda_runtime.h>
#include <cuda_bf16.h>
#include <cstdint>

#define STARTP 4080

// ---------------------------------------------------------------------------
// Device-global scratch (no allocations allowed)
// ---------------------------------------------------------------------------
__device__ float g_qkv[256 * 6144];                              // fp32 q|k|v
__device__ __nv_bfloat16 g_x_h [256*4096], g_x_l [256*4096];     // x planes
__device__ __nv_bfloat16 g_at_h[256*4096], g_at_l[256*4096];     // attn planes

// ---------------------------------------------------------------------------
// helpers
// ---------------------------------------------------------------------------
__device__ __forceinline__ uint32_t packbf(float a, float b) {  // a->lo16, b->hi16
    uint32_t u;
    asm("cvt.rn.bf16x2.f32 %0, %1, %2;" : "=r"(u) : "f"(b), "f"(a));
    return u;
}
// split pair (a,b) into bf16-hi plane word and bf16-lo (residual) plane word
__device__ __forceinline__ void split2(float a, float b, uint32_t& h, uint32_t& l) {
    h = packbf(a, b);
    float ra = a - __uint_as_float(h << 16);
    float rb = b - __uint_as_float(h & 0xffff0000u);
    l = packbf(ra, rb);
}

__device__ __forceinline__ void mma16(float* c, const uint32_t* a,
                                      uint32_t b0, uint32_t b1) {
    asm("mma.sync.aligned.m16n8k16.row.col.f32.bf16.bf16.f32 "
        "{%0,%1,%2,%3}, {%4,%5,%6,%7}, {%8,%9}, {%0,%1,%2,%3};"
        : "+f"(c[0]), "+f"(c[1]), "+f"(c[2]), "+f"(c[3])
        : "r"(a[0]), "r"(a[1]), "r"(a[2]), "r"(a[3]), "r"(b0), "r"(b1));
}

__device__ __forceinline__ void ldsm4(uint32_t* r, uint32_t addr) {
    asm volatile("ldmatrix.sync.aligned.m8n8.x4.shared.b16 {%0,%1,%2,%3}, [%4];"
        : "=r"(r[0]), "=r"(r[1]), "=r"(r[2]), "=r"(r[3]) : "r"(addr));
}
__device__ __forceinline__ void ldsm4t(uint32_t* r, uint32_t addr) {
    asm volatile("ldmatrix.sync.aligned.m8n8.x4.trans.shared.b16 {%0,%1,%2,%3}, [%4];"
        : "=r"(r[0]), "=r"(r[1]), "=r"(r[2]), "=r"(r[3]) : "r"(addr));
}

// ---------------------------------------------------------------------------
// fp32 -> bf16 hi/lo planes (only for x: 4 MB)
// ---------------------------------------------------------------------------
__global__ __launch_bounds__(256) void convert_kernel(
    const float* __restrict__ in, __nv_bfloat16* __restrict__ oh,
    __nv_bfloat16* __restrict__ ol, int n4)
{
    int i = blockIdx.x * 256 + threadIdx.x;
    if (i >= n4) return;
    float4 v = ((const float4*)in)[i];
    uint32_t h0, l0, h1, l1;
    split2(v.x, v.y, h0, l0);
    split2(v.z, v.w, h1, l1);
    ((uint2*)oh)[i] = make_uint2(h0, h1);
    ((uint2*)ol)[i] = make_uint2(l0, l1);
}

// ---------------------------------------------------------------------------
// bf16x3 GEMM with in-mainloop fp32->hi/lo split of B.
// C[M,N] = A[M,4096] @ B[4096,N] + bias (fp32 out).
// A: pre-split bf16 planes. B: fp32, register-prefetched + split in-loop.
// Block 64M x 128N, BK=32, 128 thr (warps 2m x 2n), 2-stage smem.
// ---------------------------------------------------------------------------
__global__ __launch_bounds__(128) void gemm_bf16x3(
    const __nv_bfloat16* __restrict__ Ah, const __nv_bfloat16* __restrict__ Al,
    const float* B0, int ldb0, const float* bias0, int split1,
    const float* B1, int ldb1, const float* bias1, int split2_,
    const float* B2, int ldb2, const float* bias2,
    float* __restrict__ C, int ldc)
{
    extern __shared__ char smraw[];
    __nv_bfloat16* As = (__nv_bfloat16*)smraw;      // [2][2][64][40]
    __nv_bfloat16* Bs = As + 2*2*64*40;             // [2][2][32][136]

    const int n0 = blockIdx.x * 128;
    const int m0 = blockIdx.y * 64;

    const float* Bp; int ldb; const float* bias; int nloc;
    if (n0 < split1)       { Bp = B0; ldb = ldb0; bias = bias0; nloc = n0; }
    else if (n0 < split2_) { Bp = B1; ldb = ldb1; bias = bias1; nloc = n0 - split1; }
    else                   { Bp = B2; ldb = ldb2; bias = bias2; nloc = n0 - split2_; }

    const int tid = threadIdx.x, lane = tid & 31, warp = tid >> 5;
    const int g = lane >> 2, tig = lane & 3;
    const int wm = warp & 1, wn = warp >> 1;
    const int lr = lane & 7, mt = lane >> 3;

    const uint32_t sA = (uint32_t)__cvta_generic_to_shared(As);
    const uint32_t sB = (uint32_t)__cvta_generic_to_shared(Bs);

    // prefetch mappings
    // A: 4 x uint4 (bf16 planes). idx = tid + 128*i: p=idx>>8, row=(idx&255)>>2, seg=idx&3
    // B: 8 x float4 (fp32).       idx = tid + 128*i: row=idx>>5 (0..31), c4=idx&31
    uint4  pa[4];
    float4 pb[8];

    auto fetch = [&](int ck) {
        #pragma unroll
        for (int i = 0; i < 4; ++i) {
            int idx = tid + 128 * i;
            int p = idx >> 8, rem = idx & 255, row = rem >> 2, seg = rem & 3;
            const __nv_bfloat16* src = (p ? Al : Ah)
                + (size_t)(m0 + row) * 4096 + ck * 32 + seg * 8;
            pa[i] = *(const uint4*)src;
        }
        #pragma unroll
        for (int i = 0; i < 8; ++i) {
            int idx = tid + 128 * i;
            int row = idx >> 5, c4 = idx & 31;
            pb[i] = *(const float4*)(Bp + (size_t)(ck * 32 + row) * ldb + nloc + c4 * 4);
        }
    };

    float acc[2][8][4];
    #pragma unroll
    for (int mf = 0; mf < 2; ++mf)
        #pragma unroll
        for (int nf = 0; nf < 8; ++nf)
            #pragma unroll
            for (int j = 0; j < 4; ++j) acc[mf][nf][j] = 0.f;

    fetch(0);

    for (int ck = 0; ck < 128; ++ck) {
        const int s = ck & 1;

        // store prefetched tile into stage s (A verbatim, B split hi/lo)
        #pragma unroll
        for (int i = 0; i < 4; ++i) {
            int idx = tid + 128 * i;
            int p = idx >> 8, rem = idx & 255, row = rem >> 2, seg = rem & 3;
            *(uint4*)&As[(((s*2+p)*64 + row)*40 + seg*8)] = pa[i];
        }
        #pragma unroll
        for (int i = 0; i < 8; ++i) {
            int idx = tid + 128 * i;
            int row = idx >> 5, c4 = idx & 31;
            float4 v = pb[i];
            uint32_t h0, l0, h1, l1;
            split2(v.x, v.y, h0, l0);
            split2(v.z, v.w, h1, l1);
            *(uint2*)&Bs[(((s*2+0)*32 + row)*136 + c4*4)] = make_uint2(h0, h1);
            *(uint2*)&Bs[(((s*2+1)*32 + row)*136 + c4*4)] = make_uint2(l0, l1);
        }

        if (ck + 1 < 128) fetch(ck + 1);   // issue LDGs early; consumed next iter
        __syncthreads();

        #pragma unroll
        for (int ks = 0; ks < 2; ++ks) {
            int k0 = ks * 16;
            uint32_t ah[2][4], al[2][4];
            #pragma unroll
            for (int mf = 0; mf < 2; ++mf) {
                int row = wm*32 + mf*16 + (mt & 1)*8 + lr;
                int col = k0 + (mt >> 1)*8;
                ldsm4(ah[mf], sA + (uint32_t)((((s*2+0)*64 + row)*40 + col)*2));
                ldsm4(al[mf], sA + (uint32_t)((((s*2+1)*64 + row)*40 + col)*2));
            }
            #pragma unroll
            for (int nfp = 0; nfp < 4; ++nfp) {
                int row = k0 + (mt & 1)*8 + lr;
                int col = wn*64 + (nfp*2 + (mt >> 1))*8;
                uint32_t bh[4], bl[4];
                ldsm4t(bh, sB + (uint32_t)((((s*2+0)*32 + row)*136 + col)*2));
                ldsm4t(bl, sB + (uint32_t)((((s*2+1)*32 + row)*136 + col)*2));
                #pragma unroll
                for (int h = 0; h < 2; ++h) {
                    int nf = nfp*2 + h;
                    #pragma unroll
                    for (int mf = 0; mf < 2; ++mf) {
                        mma16(acc[mf][nf], ah[mf], bh[2*h], bh[2*h+1]);
                        mma16(acc[mf][nf], ah[mf], bl[2*h], bl[2*h+1]);
                        mma16(acc[mf][nf], al[mf], bh[2*h], bh[2*h+1]);
                    }
                }
            }
        }
    }

    __syncthreads();
    #pragma unroll
    for (int mf = 0; mf < 2; ++mf) {
        int r0 = m0 + wm*32 + mf*16 + g;
        #pragma unroll
        for (int nf = 0; nf < 8; ++nf) {
            int cl = wn*64 + nf*8 + 2*tig;
            float b0v = bias[nloc + cl], b1v = bias[nloc + cl + 1];
            float2 w0, w1;
            w0.x = acc[mf][nf][0] + b0v; w0.y = acc[mf][nf][1] + b1v;
            w1.x = acc[mf][nf][2] + b0v; w1.y = acc[mf][nf][3] + b1v;
            *(float2*)(C + (size_t)r0 * ldc + n0 + cl)       = w0;
            *(float2*)(C + (size_t)(r0 + 8) * ldc + n0 + cl) = w1;
        }
    }
}

// ---------------------------------------------------------------------------
// RoPE over q (cols 0:4096) and k (cols 4096:5120) of g_qkv, in place.
// ---------------------------------------------------------------------------
__global__ __launch_bounds__(256) void rope_kernel(
    const float* __restrict__ cos_t, const float* __restrict__ sin_t)
{
    int gid = blockIdx.x * 256 + threadIdx.x;
    int m = gid / 2560;
    int j = gid - m * 2560;
    int s = m & 15;
    int col, p;
    if (j < 2048) { col = 2 * j;               p = j & 63; }
    else          { int jj = j - 2048; col = 4096 + 2 * jj; p = jj & 63; }
    float c  = cos_t[s * 64 + p];
    float sn = sin_t[s * 64 + p];
    float* ptr = g_qkv + (size_t)m * 6144 + col;
    float xr = ptr[0], xi = ptr[1];
    ptr[0] = xr * c - xi * sn;
    ptr[1] = xr * sn + xi * c;
}

// ---------------------------------------------------------------------------
// bf16x3 flash attention, warp-specialized.
// Block = (b, kvh), 256 threads. Warps 0-3: consumers (head w, MMA+softmax).
// Warps 4-7: producers (fp32 K/V loads -> hi/lo split -> smem planes).
// Output written directly as bf16 hi/lo planes for the out-projection.
// ---------------------------------------------------------------------------
__global__ __launch_bounds__(256, 1) void attn_bf16x3(
    const float* __restrict__ cache_k, const float* __restrict__ cache_v)
{
    extern __shared__ char smraw[];
    __nv_bfloat16* Kh = (__nv_bfloat16*)smraw;   // [2][64][136]
    __nv_bfloat16* Kl = Kh + 2*8704;
    __nv_bfloat16* Vh = Kl + 2*8704;
    __nv_bfloat16* Vl = Vh + 2*8704;
    float* Qs = (float*)smraw;                   // staging only (pre-loop)

    const int tid = threadIdx.x, lane = tid & 31, w = tid >> 5;
    const int g = lane >> 2, tig = lane & 3;
    const int lr = lane & 7, mt = lane >> 3;
    const int b = blockIdx.x >> 3, kvh = blockIdx.x & 7;
    const int ptid = tid & 127;                  // producer linear id
    const float scale = 0.08838834764831843f;    // 1/sqrt(128)
    const float* qkv = g_qkv;

    // ---- stage Q (scaled fp32) ----
    for (int i = tid; i < 64 * 32; i += 256) {
        int r = i >> 5, c4 = (i & 31) << 2;
        const float* src = qkv + (size_t)(b * 16 + (r & 15)) * 6144
                         + (kvh * 4 + (r >> 4)) * 128 + c4;
        float4 v = *(const float4*)src;
        Qs[r * 132 + c4 + 0] = v.x * scale;
        Qs[r * 132 + c4 + 1] = v.y * scale;
        Qs[r * 132 + c4 + 2] = v.z * scale;
        Qs[r * 132 + c4 + 3] = v.w * scale;
    }
    __syncthreads();

    // consumers lift Q to bf16 hi/lo fragments
    uint32_t qh[8][4], ql[8][4];
    if (w < 4) {
        #pragma unroll
        for (int kk = 0; kk < 8; ++kk) {
            const float* r0 = Qs + (w*16 + g    ) * 132 + kk*16;
            const float* r1 = Qs + (w*16 + g + 8) * 132 + kk*16;
            split2(r0[2*tig],     r0[2*tig + 1], qh[kk][0], ql[kk][0]);
            split2(r1[2*tig],     r1[2*tig + 1], qh[kk][1], ql[kk][1]);
            split2(r0[2*tig + 8], r0[2*tig + 9], qh[kk][2], ql[kk][2]);
            split2(r1[2*tig + 8], r1[2*tig + 9], qh[kk][3], ql[kk][3]);
        }
    }
    __syncthreads();   // Qs region free; producers may overwrite (K planes)

    const uint32_t kh_b = (uint32_t)__cvta_generic_to_shared(Kh);
    const uint32_t kl_b = (uint32_t)__cvta_generic_to_shared(Kl);
    const uint32_t vh_b = (uint32_t)__cvta_generic_to_shared(Vh);
    const uint32_t vl_b = (uint32_t)__cvta_generic_to_shared(Vl);

    float oacc[16][4];
    #pragma unroll
    for (int i = 0; i < 16; ++i)
        #pragma unroll
        for (int j = 0; j < 4; ++j) oacc[i][j] = 0.f;
    float mA = -1e30f, mB = -1e30f, lA = 0.f, lB = 0.f;

    // producer warps: load fp32 K/V tile, split, store bf16 planes
    auto produce = [&](int t) {
        int s = t & 1;
        #pragma unroll 4
        for (int i = 0; i < 16; ++i) {
            int id = ptid + 128 * i;
            int row = id >> 5, c4 = (id & 31) << 2;
            int key = t * 64 + row;
            const float *ks, *vs;
            if (key < STARTP) {
                size_t base = ((size_t)(b * 4096 + key) * 8 + kvh) * 128 + c4;
                ks = cache_k + base; vs = cache_v + base;
            } else {
                size_t rb = (size_t)(b * 16 + key - STARTP) * 6144 + kvh * 128 + c4;
                ks = qkv + rb + 4096; vs = qkv + rb + 5120;
            }
            float4 kv = *(const float4*)ks;
            float4 vv = *(const float4*)vs;
            uint32_t h0, l0, h1, l1;
            int e = s * 8704 + row * 136 + c4;
            split2(kv.x, kv.y, h0, l0); split2(kv.z, kv.w, h1, l1);
            *(uint32_t*)&Kh[e] = h0; *(uint32_t*)&Kh[e + 2] = h1;
            *(uint32_t*)&Kl[e] = l0; *(uint32_t*)&Kl[e + 2] = l1;
            split2(vv.x, vv.y, h0, l0); split2(vv.z, vv.w, h1, l1);
            *(uint32_t*)&Vh[e] = h0; *(uint32_t*)&Vh[e + 2] = h1;
            *(uint32_t*)&Vl[e] = l0; *(uint32_t*)&Vl[e + 2] = l1;
        }
    };

    if (w >= 4) produce(0);
    __syncthreads();

    for (int t = 0; t < 64; ++t) {
        const int s = t & 1;

        if (w >= 4) {
            // ---- producer path: fill stage s^1 with tile t+1 ----
            if (t + 1 < 64) produce(t + 1);
        } else {
            // ---- consumer path: S = Q K^T (16 rows x 64 keys) ----
            float sacc[8][4];
            #pragma unroll
            for (int nf = 0; nf < 8; ++nf)
                #pragma unroll
                for (int j = 0; j < 4; ++j) sacc[nf][j] = 0.f;

            #pragma unroll
            for (int kk = 0; kk < 8; ++kk) {
                #pragma unroll
                for (int nfp = 0; nfp < 4; ++nfp) {
                    int row = (nfp*2 + (mt >> 1))*8 + lr;          // key
                    int col = kk*16 + (mt & 1)*8;                  // hd
                    uint32_t off = (uint32_t)((s*8704 + row*136 + col)*2);
                    uint32_t bh[4], bl[4];
                    ldsm4(bh, kh_b + off);
                    ldsm4(bl, kl_b + off);
                    #pragma unroll
                    for (int h = 0; h < 2; ++h) {
                        int nf = nfp*2 + h;
                        mma16(sacc[nf], qh[kk], bh[2*h], bh[2*h+1]);
                        mma16(sacc[nf], qh[kk], bl[2*h], bl[2*h+1]);
                        mma16(sacc[nf], ql[kk], bh[2*h], bh[2*h+1]);
                    }
                }
            }

            if (t == 63) {  // causal mask, analytic
                #pragma unroll
                for (int nf = 0; nf < 8; ++nf) {
                    int key = 4032 + nf * 8 + 2 * tig;
                    if (key     > STARTP + g)     sacc[nf][0] = -1e30f;
                    if (key + 1 > STARTP + g)     sacc[nf][1] = -1e30f;
                    if (key     > STARTP + g + 8) sacc[nf][2] = -1e30f;
                    if (key + 1 > STARTP + g + 8) sacc[nf][3] = -1e30f;
                }
            }

            // ---- online softmax (rows g and g+8) ----
            float tmA = -1e30f, tmB = -1e30f;
            #pragma unroll
            for (int nf = 0; nf < 8; ++nf) {
                tmA = fmaxf(tmA, fmaxf(sacc[nf][0], sacc[nf][1]));
                tmB = fmaxf(tmB, fmaxf(sacc[nf][2], sacc[nf][3]));
            }
            tmA = fmaxf(tmA, __shfl_xor_sync(0xffffffffu, tmA, 1));
            tmA = fmaxf(tmA, __shfl_xor_sync(0xffffffffu, tmA, 2));
            tmB = fmaxf(tmB, __shfl_xor_sync(0xffffffffu, tmB, 1));
            tmB = fmaxf(tmB, __shfl_xor_sync(0xffffffffu, tmB, 2));

            float mnA = fmaxf(mA, tmA), mnB = fmaxf(mB, tmB);
            float cA = __expf(mA - mnA), cB = __expf(mB - mnB);
            float psA = 0.f, psB = 0.f;
            #pragma unroll
            for (int nf = 0; nf < 8; ++nf) {
                sacc[nf][0] = __expf(sacc[nf][0] - mnA);
                sacc[nf][1] = __expf(sacc[nf][1] - mnA);
                sacc[nf][2] = __expf(sacc[nf][2] - mnB);
                sacc[nf][3] = __expf(sacc[nf][3] - mnB);
                psA += sacc[nf][0] + sacc[nf][1];
                psB += sacc[nf][2] + sacc[nf][3];
            }
            psA += __shfl_xor_sync(0xffffffffu, psA, 1);
            psA += __shfl_xor_sync(0xffffffffu, psA, 2);
            psB += __shfl_xor_sync(0xffffffffu, psB, 1);
            psB += __shfl_xor_sync(0xffffffffu, psB, 2);
            lA = lA * cA + psA; lB = lB * cB + psB;
            mA = mnA; mB = mnB;
            #pragma unroll
            for (int i = 0; i < 16; ++i) {
                oacc[i][0] *= cA; oacc[i][1] *= cA;
                oacc[i][2] *= cB; oacc[i][3] *= cB;
            }

            // ---- O += P V (P fragments straight from sacc registers) ----
            #pragma unroll
            for (int kf = 0; kf < 4; ++kf) {
                uint32_t pah[4], pal[4];
                split2(sacc[2*kf][0],   sacc[2*kf][1],   pah[0], pal[0]);
                split2(sacc[2*kf][2],   sacc[2*kf][3],   pah[1], pal[1]);
                split2(sacc[2*kf+1][0], sacc[2*kf+1][1], pah[2], pal[2]);
                split2(sacc[2*kf+1][2], sacc[2*kf+1][3], pah[3], pal[3]);
                #pragma unroll
                for (int np = 0; np < 8; ++np) {
                    int row = kf*16 + (mt & 1)*8 + lr;             // key
                    int col = (np*2 + (mt >> 1))*8;                // d
                    uint32_t off = (uint32_t)((s*8704 + row*136 + col)*2);
                    uint32_t vh[4], vl[4];
                    ldsm4t(vh, vh_b + off);
                    ldsm4t(vl, vl_b + off);
                    #pragma unroll
                    for (int h = 0; h < 2; ++h) {
                        int nf2 = np*2 + h;
                        mma16(oacc[nf2], pah, vh[2*h], vh[2*h+1]);
                        mma16(oacc[nf2], pah, vl[2*h], vl[2*h+1]);
                        mma16(oacc[nf2], pal, vh[2*h], vh[2*h+1]);
                    }
                }
            }
        }
        __syncthreads();   // stage s consumed; stage s^1 stores visible
    }

    // ---- finalize: consumers write bf16 hi/lo planes ----
    if (w < 4) {
        float rAi = 1.f / lA, rBi = 1.f / lB;
        size_t baseA = (size_t)(b*16 + g    ) * 4096 + (kvh*4 + w) * 128;
        size_t baseB = (size_t)(b*16 + g + 8) * 4096 + (kvh*4 + w) * 128;
        #pragma unroll
        for (int nf2 = 0; nf2 < 16; ++nf2) {
            int col = nf2*8 + 2*tig;
            uint32_t h, l;
            split2(oacc[nf2][0]*rAi, oacc[nf2][1]*rAi, h, l);
            *(uint32_t*)&g_at_h[baseA + col] = h;
            *(uint32_t*)&g_at_l[baseA + col] = l;
            split2(oacc[nf2][2]*rBi, oacc[nf2][3]*rBi, h, l);
            *(uint32_t*)&g_at_h[baseB + col] = h;
            *(uint32_t*)&g_at_l[baseB + col] = l;
        }
    }
}

// ---------------------------------------------------------------------------
extern "C" void kernel_launch(void* const* d_in, const int* in_sizes, int n_in,
                              void* d_out, int out_size)
{
    const float* x  = (const float*)d_in[0];
    const float* fc = (const float*)d_in[1];
    const float* fs = (const float*)d_in[2];
    const float* ck = (const float*)d_in[4];
    const float* cv = (const float*)d_in[5];
    const float* wq = (const float*)d_in[6];
    const float* bq = (const float*)d_in[7];
    const float* wk = (const float*)d_in[8];
    const float* bk = (const float*)d_in[9];
    const float* wv = (const float*)d_in[10];
    const float* bv = (const float*)d_in[11];
    const float* wo = (const float*)d_in[12];
    const float* bo = (const float*)d_in[13];
    float* out = (float*)d_out;

    __nv_bfloat16 *x_h, *x_l, *at_h, *at_l;
    float* qkv;
    cudaGetSymbolAddress((void**)&x_h,  g_x_h);  cudaGetSymbolAddress((void**)&x_l,  g_x_l);
    cudaGetSymbolAddress((void**)&at_h, g_at_h); cudaGetSymbolAddress((void**)&at_l, g_at_l);
    cudaGetSymbolAddress((void**)&qkv,  g_qkv);

    const int gemm_smem = (2*2*64*40 + 2*2*32*136) * 2;   // 55296 B
    const int attn_smem = 4 * 2 * 8704 * 2;               // 139264 B
    cudaFuncSetAttribute(gemm_bf16x3,
                         cudaFuncAttributeMaxDynamicSharedMemorySize, gemm_smem);
    cudaFuncSetAttribute(attn_bf16x3,
                         cudaFuncAttributeMaxDynamicSharedMemorySize, attn_smem);

    // 1) split x -> bf16 planes (weights are split in-GEMM)
    convert_kernel<<<1024, 256>>>(x, x_h, x_l, 256*4096/4);

    // 2) fused QKV projection (fp32 out into g_qkv)
    gemm_bf16x3<<<dim3(48, 4), 128, gemm_smem>>>(
        x_h, x_l,
        wq, 4096, bq, 4096,
        wk, 1024, bk, 5120,
        wv, 1024, bv,
        qkv, 6144);

    // 3) RoPE on q and k
    rope_kernel<<<2560, 256>>>(fc, fs);

    // 4) attention (warp-specialized; writes bf16 hi/lo planes)
    attn_bf16x3<<<128, 256, attn_smem>>>(ck, cv);

    // 5) output projection -> d_out (fp32)
    gemm_bf16x3<<<dim3(32, 4), 128, gemm_smem>>>(
        at_h, at_l,
        wo, 4096, bo, 1 << 30,
        wo, 4096, bo, 1 << 30,
        wo, 4096, bo,
        out, 4096);
}